// round 8
// baseline (speedup 1.0000x reference)
#include <cuda_runtime.h>
#include <cuda_fp16.h>

#define N_NODES 100000
#define N_EDGES 1600000
#define F 64
#define SCAN_B 512
#define N_SCANB ((N_NODES + SCAN_B - 1) / SCAN_B)   // 196

// ---- scratch (static __device__, no allocation) ----
__device__ int     g_is64;                 // 1 if edge_index is int64, 0 if int32
__device__ int     g_done;                 // last-block-done counter for the scan
__device__ int     g_indeg[N_NODES];
__device__ int     g_start[N_NODES];       // local-exclusive (within scan block)
__device__ int     g_cur[N_NODES];         // local bump counters
__device__ int     g_bsum[SCAN_B];
__device__ int     g_boff[SCAN_B];         // exclusive block offsets
__device__ float   g_dinv[N_NODES];
__device__ int     g_csr[N_EDGES];         // src node per CSR slot (grouped by dst)
__device__ __half2 g_hsh[N_NODES * 32];    // (x @ W) * dinv[row], fp16 pairs
__device__ float   g_z[N_NODES * F];       // layer-1 activations (fp32)

// ---------------------------------------------------------------------------
__global__ void k_init(const long long* __restrict__ p64) {
    int i = blockIdx.x * blockDim.x + threadIdx.x;
    if (i < N_NODES) g_indeg[i] = 0;
    if (i == 0) g_done = 0;
    if (blockIdx.x == 0) {
        __shared__ int ok;
        if (threadIdx.x == 0) ok = 1;
        __syncthreads();
        if (threadIdx.x < 64) {
            long long v = p64[threadIdx.x];
            if (v < 0 || v >= N_NODES) ok = 0;
        }
        __syncthreads();
        if (threadIdx.x == 0) g_is64 = ok;
    }
}

__global__ void k_count(const void* __restrict__ ei) {
    int e = blockIdx.x * blockDim.x + threadIdx.x;
    if (e >= N_EDGES) return;
    int d = g_is64 ? (int)((const long long*)ei)[N_EDGES + e]
                   : ((const int*)ei)[N_EDGES + e];
    if ((unsigned)d < N_NODES) atomicAdd(&g_indeg[d], 1);
}

// ---------------------------------------------------------------------------
// Single-kernel scan (last-done-block pattern). Consumers add g_boff[node>>9].
// ---------------------------------------------------------------------------
__global__ void __launch_bounds__(SCAN_B) k_scan() {
    __shared__ int sh[SCAN_B];
    __shared__ int amLast;
    int i = blockIdx.x * SCAN_B + threadIdx.x;
    int v = (i < N_NODES) ? g_indeg[i] : 0;
    sh[threadIdx.x] = v;
    __syncthreads();
    for (int off = 1; off < SCAN_B; off <<= 1) {
        int t = (threadIdx.x >= off) ? sh[threadIdx.x - off] : 0;
        __syncthreads();
        sh[threadIdx.x] += t;
        __syncthreads();
    }
    if (i < N_NODES) {
        int ex = sh[threadIdx.x] - v;
        g_start[i] = ex;
        g_cur[i]   = ex;
        g_dinv[i]  = rsqrtf((float)(v + 1));   // +1 self loop
    }
    if (threadIdx.x == SCAN_B - 1) g_bsum[blockIdx.x] = sh[SCAN_B - 1];
    __threadfence();
    __syncthreads();
    if (threadIdx.x == 0)
        amLast = (atomicAdd(&g_done, 1) == (int)gridDim.x - 1);
    __syncthreads();
    if (amLast) {
        __threadfence();
        int bv = (threadIdx.x < N_SCANB) ? g_bsum[threadIdx.x] : 0;
        sh[threadIdx.x] = bv;
        __syncthreads();
        for (int off = 1; off < SCAN_B; off <<= 1) {
            int t = (threadIdx.x >= off) ? sh[threadIdx.x - off] : 0;
            __syncthreads();
            sh[threadIdx.x] += t;
            __syncthreads();
        }
        if (threadIdx.x < N_SCANB) g_boff[threadIdx.x] = sh[threadIdx.x] - bv;
    }
}

__global__ void k_fill(const void* __restrict__ ei) {
    int e = blockIdx.x * blockDim.x + threadIdx.x;
    if (e >= N_EDGES) return;
    int s, d;
    if (g_is64) {
        s = (int)((const long long*)ei)[e];
        d = (int)((const long long*)ei)[N_EDGES + e];
    } else {
        s = ((const int*)ei)[e];
        d = ((const int*)ei)[N_EDGES + e];
    }
    if ((unsigned)s < N_NODES && (unsigned)d < N_NODES) {
        int slot = atomicAdd(&g_cur[d], 1) + g_boff[d >> 9];
        if ((unsigned)slot < N_EDGES) g_csr[slot] = s;
    }
}

// ---------------------------------------------------------------------------
// hs = (X @ W) * dinv[row], stored fp16.
// 8x8 register tile: 64x64 block tile, 64 threads (tx,ty in 8x8 grid),
// each thread owns rows ty*8..+7 x cols tx*8..+7.
// LDS per k per thread: 2 float4 of X + 2 float4 of W = 64B for 64 FFMA.
//   L == 0: X = harness input (raw h);  L == 1: X = g_z (device symbol)
// ---------------------------------------------------------------------------
#define XT_PITCH 68   // 64 + 4 pad (float units); keeps 16B alignment per k-row
template <int L>
__global__ void __launch_bounds__(64) k_gemm(const float* __restrict__ Xin,
                                             const float* __restrict__ W) {
    __shared__ float Ws[64 * 64];
    __shared__ float XsT[64 * XT_PITCH];

    const float* __restrict__ X = (L == 0) ? Xin : (const float*)g_z;

    const int tx = threadIdx.x & 7;
    const int ty = threadIdx.x >> 3;
    const int tid = threadIdx.x;
    const int rowbase = blockIdx.x * 64;

    #pragma unroll
    for (int i = tid; i < 64 * 64; i += 64) Ws[i] = W[i];
    #pragma unroll
    for (int i = tid; i < 64 * 64; i += 64) {
        int r = i >> 6, c = i & 63;
        int row = rowbase + r;
        float v = (row < N_NODES) ? X[row * 64 + c] : 0.0f;
        XsT[c * XT_PITCH + r] = v;
    }
    __syncthreads();

    float acc[8][8];
    #pragma unroll
    for (int i = 0; i < 8; i++)
        #pragma unroll
        for (int j = 0; j < 8; j++) acc[i][j] = 0.0f;

    #pragma unroll 4
    for (int k = 0; k < 64; k++) {
        float4 xa = *(const float4*)&XsT[k * XT_PITCH + ty * 8];
        float4 xb = *(const float4*)&XsT[k * XT_PITCH + ty * 8 + 4];
        float4 wa = *(const float4*)&Ws[k * 64 + tx * 8];
        float4 wb = *(const float4*)&Ws[k * 64 + tx * 8 + 4];
        float xr[8] = {xa.x, xa.y, xa.z, xa.w, xb.x, xb.y, xb.z, xb.w};
        float wc[8] = {wa.x, wa.y, wa.z, wa.w, wb.x, wb.y, wb.z, wb.w};
        #pragma unroll
        for (int i = 0; i < 8; i++)
            #pragma unroll
            for (int j = 0; j < 8; j++)
                acc[i][j] += xr[i] * wc[j];
    }

    #pragma unroll
    for (int i = 0; i < 8; i++) {
        int row = rowbase + ty * 8 + i;
        if (row < N_NODES) {
            float di = g_dinv[row];
            __half2 h0 = __floats2half2_rn(acc[i][0] * di, acc[i][1] * di);
            __half2 h1 = __floats2half2_rn(acc[i][2] * di, acc[i][3] * di);
            __half2 h2 = __floats2half2_rn(acc[i][4] * di, acc[i][5] * di);
            __half2 h3 = __floats2half2_rn(acc[i][6] * di, acc[i][7] * di);
            uint4 pk;
            pk.x = *(const unsigned int*)&h0;
            pk.y = *(const unsigned int*)&h1;
            pk.z = *(const unsigned int*)&h2;
            pk.w = *(const unsigned int*)&h3;
            // cols tx*8..tx*8+7 -> half2 slots row*32 + tx*4 .. +3 (16B store)
            *(uint4*)&g_hsh[row * 32 + tx * 4] = pk;
        }
    }
}

// ---------------------------------------------------------------------------
// z[node] = relu( dinv[node] * (hs[node] + sum_{neigh} hs[s]) + b )
// One warp per node; lane owns half2 slot `lane`; fp32 accum; unroll x8.
// FUSE_OUT == 0: write z to g_z.   FUSE_OUT == 1: fused linear readout.
// ---------------------------------------------------------------------------
template <int FUSE_OUT>
__global__ void __launch_bounds__(256) k_aggregate(const float* __restrict__ b,
                                                   const float* __restrict__ Wo,
                                                   const float* __restrict__ bo,
                                                   float* __restrict__ out) {
    const int t = blockIdx.x * blockDim.x + threadIdx.x;
    const int node = t >> 5;
    if (node >= N_NODES) return;
    const int lane = t & 31;

    float2 acc = __half22float2(g_hsh[node * 32 + lane]);  // self loop

    int e   = g_start[node] + g_boff[node >> 9];
    const int end = e + g_indeg[node];

    for (; e + 8 <= end; e += 8) {
        int s0 = __ldg(&g_csr[e]);
        int s1 = __ldg(&g_csr[e + 1]);
        int s2 = __ldg(&g_csr[e + 2]);
        int s3 = __ldg(&g_csr[e + 3]);
        int s4 = __ldg(&g_csr[e + 4]);
        int s5 = __ldg(&g_csr[e + 5]);
        int s6 = __ldg(&g_csr[e + 6]);
        int s7 = __ldg(&g_csr[e + 7]);
        float2 v0 = __half22float2(__ldg(&g_hsh[s0 * 32 + lane]));
        float2 v1 = __half22float2(__ldg(&g_hsh[s1 * 32 + lane]));
        float2 v2 = __half22float2(__ldg(&g_hsh[s2 * 32 + lane]));
        float2 v3 = __half22float2(__ldg(&g_hsh[s3 * 32 + lane]));
        float2 v4 = __half22float2(__ldg(&g_hsh[s4 * 32 + lane]));
        float2 v5 = __half22float2(__ldg(&g_hsh[s5 * 32 + lane]));
        float2 v6 = __half22float2(__ldg(&g_hsh[s6 * 32 + lane]));
        float2 v7 = __half22float2(__ldg(&g_hsh[s7 * 32 + lane]));
        acc.x += ((v0.x + v1.x) + (v2.x + v3.x)) + ((v4.x + v5.x) + (v6.x + v7.x));
        acc.y += ((v0.y + v1.y) + (v2.y + v3.y)) + ((v4.y + v5.y) + (v6.y + v7.y));
    }
    for (; e < end; e++) {
        int s = __ldg(&g_csr[e]);
        float2 v = __half22float2(__ldg(&g_hsh[s * 32 + lane]));
        acc.x += v.x; acc.y += v.y;
    }

    const float di = g_dinv[node];
    const int c = lane * 2;
    float2 bb = *(const float2*)(b + c);
    float zx = fmaxf(acc.x * di + bb.x, 0.0f);
    float zy = fmaxf(acc.y * di + bb.y, 0.0f);

    if constexpr (FUSE_OUT == 0) {
        *(float2*)(g_z + node * 64 + c) = make_float2(zx, zy);
    } else {
        float2 w = *(const float2*)(Wo + c);
        float sum = zx * w.x + zy * w.y;
        #pragma unroll
        for (int off = 16; off; off >>= 1)
            sum += __shfl_down_sync(0xffffffff, sum, off);
        if (lane == 0) out[node] = sum + bo[0];
    }
}

// ---------------------------------------------------------------------------
extern "C" void kernel_launch(void* const* d_in, const int* in_sizes, int n_in,
                              void* d_out, int out_size) {
    const float* h  = (const float*)d_in[0];
    const void*  ei = d_in[1];               // [2,E]; dtype probed on device
    const float* W1 = (const float*)d_in[2];
    const float* b1 = (const float*)d_in[3];
    const float* W2 = (const float*)d_in[4];
    const float* b2 = (const float*)d_in[5];
    const float* Wo = (const float*)d_in[6];
    const float* bo = (const float*)d_in[7];
    float* out = (float*)d_out;

    cudaStream_t s2;
    cudaStreamCreateWithFlags(&s2, cudaStreamNonBlocking);
    cudaEvent_t eFork, eJoin;
    cudaEventCreateWithFlags(&eFork, cudaEventDisableTiming);
    cudaEventCreateWithFlags(&eJoin, cudaEventDisableTiming);

    // Main stream: init, count, scan (produces dinv needed by gemm epilogue).
    k_init<<<(N_NODES + 255) / 256, 256>>>((const long long*)ei);
    k_count<<<(N_EDGES + 255) / 256, 256>>>(ei);
    k_scan<<<N_SCANB, SCAN_B>>>();

    // Fork gemm0 to overlap with k_fill.
    cudaEventRecord(eFork, 0);
    cudaStreamWaitEvent(s2, eFork, 0);
    k_gemm<0><<<(N_NODES + 63) / 64, 64, 0, s2>>>(h, W1);
    cudaEventRecord(eJoin, s2);

    k_fill<<<(N_EDGES + 255) / 256, 256>>>(ei);

    cudaStreamWaitEvent(0, eJoin, 0);
    k_aggregate<0><<<(N_NODES * 32 + 255) / 256, 256>>>(b1, nullptr, nullptr, nullptr);
    k_gemm<1><<<(N_NODES + 63) / 64, 64>>>(nullptr, W2);
    k_aggregate<1><<<(N_NODES * 32 + 255) / 256, 256>>>(b2, Wo, bo, out);

    cudaEventDestroy(eFork);
    cudaEventDestroy(eJoin);
    cudaStreamDestroy(s2);
}

// round 9
// speedup vs baseline: 1.1076x; 1.1076x over previous
#include <cuda_runtime.h>
#include <cuda_fp16.h>

#define N_NODES 100000
#define N_EDGES 1600000
#define F 64
#define SCAN_B 512
#define N_SCANB ((N_NODES + SCAN_B - 1) / SCAN_B)   // 196

// ---- scratch (static __device__, no allocation) ----
__device__ int     g_is64;                 // 1 if edge_index is int64, 0 if int32
__device__ int     g_done;                 // last-block-done counter for the scan
__device__ int     g_indeg[N_NODES];
__device__ int     g_start[N_NODES];       // local-exclusive (within scan block)
__device__ int     g_cur[N_NODES];         // local bump counters
__device__ int     g_bsum[SCAN_B];
__device__ int     g_boff[SCAN_B];         // exclusive block offsets
__device__ float   g_dinv[N_NODES];
__device__ int     g_csr[N_EDGES];         // src node per CSR slot (grouped by dst)
__device__ __half2 g_hsh[N_NODES * 32];    // (x @ W) * dinv[row], fp16 pairs
__device__ float   g_z[N_NODES * F];       // layer-1 activations (fp32)

// ---------------------------------------------------------------------------
__global__ void k_init(const long long* __restrict__ p64) {
    int i = blockIdx.x * blockDim.x + threadIdx.x;
    if (i < N_NODES) g_indeg[i] = 0;
    if (i == 0) g_done = 0;
    if (blockIdx.x == 0) {
        __shared__ int ok;
        if (threadIdx.x == 0) ok = 1;
        __syncthreads();
        if (threadIdx.x < 64) {
            long long v = p64[threadIdx.x];
            if (v < 0 || v >= N_NODES) ok = 0;
        }
        __syncthreads();
        if (threadIdx.x == 0) g_is64 = ok;
    }
}

__global__ void k_count(const void* __restrict__ ei) {
    int e = blockIdx.x * blockDim.x + threadIdx.x;
    if (e >= N_EDGES) return;
    int d = g_is64 ? (int)((const long long*)ei)[N_EDGES + e]
                   : ((const int*)ei)[N_EDGES + e];
    if ((unsigned)d < N_NODES) atomicAdd(&g_indeg[d], 1);
}

// ---------------------------------------------------------------------------
// Single-kernel scan (last-done-block pattern). Consumers add g_boff[node>>9].
// ---------------------------------------------------------------------------
__global__ void __launch_bounds__(SCAN_B) k_scan() {
    __shared__ int sh[SCAN_B];
    __shared__ int amLast;
    int i = blockIdx.x * SCAN_B + threadIdx.x;
    int v = (i < N_NODES) ? g_indeg[i] : 0;
    sh[threadIdx.x] = v;
    __syncthreads();
    for (int off = 1; off < SCAN_B; off <<= 1) {
        int t = (threadIdx.x >= off) ? sh[threadIdx.x - off] : 0;
        __syncthreads();
        sh[threadIdx.x] += t;
        __syncthreads();
    }
    if (i < N_NODES) {
        int ex = sh[threadIdx.x] - v;
        g_start[i] = ex;
        g_cur[i]   = ex;
        g_dinv[i]  = rsqrtf((float)(v + 1));   // +1 self loop
    }
    if (threadIdx.x == SCAN_B - 1) g_bsum[blockIdx.x] = sh[SCAN_B - 1];
    __threadfence();
    __syncthreads();
    if (threadIdx.x == 0)
        amLast = (atomicAdd(&g_done, 1) == (int)gridDim.x - 1);
    __syncthreads();
    if (amLast) {
        __threadfence();
        int bv = (threadIdx.x < N_SCANB) ? g_bsum[threadIdx.x] : 0;
        sh[threadIdx.x] = bv;
        __syncthreads();
        for (int off = 1; off < SCAN_B; off <<= 1) {
            int t = (threadIdx.x >= off) ? sh[threadIdx.x - off] : 0;
            __syncthreads();
            sh[threadIdx.x] += t;
            __syncthreads();
        }
        if (threadIdx.x < N_SCANB) g_boff[threadIdx.x] = sh[threadIdx.x] - bv;
    }
}

__global__ void k_fill(const void* __restrict__ ei) {
    int e = blockIdx.x * blockDim.x + threadIdx.x;
    if (e >= N_EDGES) return;
    int s, d;
    if (g_is64) {
        s = (int)((const long long*)ei)[e];
        d = (int)((const long long*)ei)[N_EDGES + e];
    } else {
        s = ((const int*)ei)[e];
        d = ((const int*)ei)[N_EDGES + e];
    }
    if ((unsigned)s < N_NODES && (unsigned)d < N_NODES) {
        int slot = atomicAdd(&g_cur[d], 1) + g_boff[d >> 9];
        if ((unsigned)slot < N_EDGES) g_csr[slot] = s;
    }
}

// ---------------------------------------------------------------------------
// Tensor-core GEMM (tf32 m16n8k8): hs = (X @ W) * dinv[row], stored fp16.
// 64x64 tile, 256 threads = 8 warps; warp w: rows (w&3)*16, cols (w>>2)*32,
// 4 m16n8 tiles per warp sharing one A fragment per k-step.
// Smem pitches chosen for conflict-free fragment gathers:
//   Xs pitch 68 (68 % 32 == 4 -> bank 4r+c bijective on r0..7 x c0..3)
//   Ws pitch 72 (72 % 32 == 8 -> bank 8k+n bijective on k0..3 x n0..7)
//   L == 0: X = harness input (raw h);  L == 1: X = g_z (device symbol)
// ---------------------------------------------------------------------------
#define XP 68
#define WP 72

__device__ __forceinline__ unsigned f2tf32(float f) {
    unsigned r;
    asm("cvt.rna.tf32.f32 %0, %1;" : "=r"(r) : "f"(f));
    return r;
}

template <int L>
__global__ void __launch_bounds__(256) k_gemm(const float* __restrict__ Xin,
                                              const float* __restrict__ W) {
    __shared__ unsigned Xs[64 * XP];
    __shared__ unsigned Ws[64 * WP];

    const float* __restrict__ X = (L == 0) ? Xin : (const float*)g_z;

    const int tid = threadIdx.x;
    const int rowbase = blockIdx.x * 64;

    // Stage + convert to tf32
    #pragma unroll
    for (int i = tid; i < 64 * 64; i += 256) {
        int k = i >> 6, n = i & 63;
        Ws[k * WP + n] = f2tf32(W[i]);
    }
    #pragma unroll
    for (int i = tid; i < 64 * 64; i += 256) {
        int r = i >> 6, c = i & 63;
        int row = rowbase + r;
        float v = (row < N_NODES) ? X[row * 64 + c] : 0.0f;
        Xs[r * XP + c] = f2tf32(v);
    }
    __syncthreads();

    const int warp = tid >> 5;
    const int lane = tid & 31;
    const int gid  = lane >> 2;     // 0..7
    const int tg   = lane & 3;      // 0..3
    const int wr   = (warp & 3) * 16;   // warp row base in tile
    const int wc   = (warp >> 2) * 32;  // warp col base in tile

    float4 acc[4] = {{0,0,0,0},{0,0,0,0},{0,0,0,0},{0,0,0,0}};

    #pragma unroll
    for (int kb = 0; kb < 64; kb += 8) {
        const unsigned* xrow = &Xs[(wr + gid) * XP + kb + tg];
        unsigned a0 = xrow[0];
        unsigned a1 = xrow[8 * XP];
        unsigned a2 = xrow[4];
        unsigned a3 = xrow[8 * XP + 4];
        #pragma unroll
        for (int t = 0; t < 4; t++) {
            const unsigned* wcol = &Ws[(kb + tg) * WP + wc + t * 8 + gid];
            unsigned b0 = wcol[0];
            unsigned b1 = wcol[4 * WP];
            asm volatile(
                "mma.sync.aligned.m16n8k8.row.col.f32.tf32.tf32.f32 "
                "{%0,%1,%2,%3}, {%4,%5,%6,%7}, {%8,%9}, {%0,%1,%2,%3};"
                : "+f"(acc[t].x), "+f"(acc[t].y), "+f"(acc[t].z), "+f"(acc[t].w)
                : "r"(a0), "r"(a1), "r"(a2), "r"(a3), "r"(b0), "r"(b1));
        }
    }

    // Epilogue: scale by dinv, pack fp16 pairs.
    // c0,c1 = rows wr+gid, cols wc+t*8+2tg(+1);  c2,c3 = row +8.
    const int r0 = rowbase + wr + gid;
    const int r1 = r0 + 8;
    const float d0 = (r0 < N_NODES) ? g_dinv[r0] : 0.0f;
    const float d1 = (r1 < N_NODES) ? g_dinv[r1] : 0.0f;
    #pragma unroll
    for (int t = 0; t < 4; t++) {
        int slot = (wc >> 1) + t * 4 + tg;   // half2 slot = col/2
        if (r0 < N_NODES)
            g_hsh[r0 * 32 + slot] = __floats2half2_rn(acc[t].x * d0, acc[t].y * d0);
        if (r1 < N_NODES)
            g_hsh[r1 * 32 + slot] = __floats2half2_rn(acc[t].z * d1, acc[t].w * d1);
    }
}

// ---------------------------------------------------------------------------
// z[node] = relu( dinv[node] * (hs[node] + sum_{neigh} hs[s]) + b )
// One warp per node; lane owns half2 slot `lane`; fp32 accum; unroll x8.
// FUSE_OUT == 0: write z to g_z.   FUSE_OUT == 1: fused linear readout.
// ---------------------------------------------------------------------------
template <int FUSE_OUT>
__global__ void __launch_bounds__(256) k_aggregate(const float* __restrict__ b,
                                                   const float* __restrict__ Wo,
                                                   const float* __restrict__ bo,
                                                   float* __restrict__ out) {
    const int t = blockIdx.x * blockDim.x + threadIdx.x;
    const int node = t >> 5;
    if (node >= N_NODES) return;
    const int lane = t & 31;

    float2 acc = __half22float2(g_hsh[node * 32 + lane]);  // self loop

    int e   = g_start[node] + g_boff[node >> 9];
    const int end = e + g_indeg[node];

    for (; e + 8 <= end; e += 8) {
        int s0 = __ldg(&g_csr[e]);
        int s1 = __ldg(&g_csr[e + 1]);
        int s2 = __ldg(&g_csr[e + 2]);
        int s3 = __ldg(&g_csr[e + 3]);
        int s4 = __ldg(&g_csr[e + 4]);
        int s5 = __ldg(&g_csr[e + 5]);
        int s6 = __ldg(&g_csr[e + 6]);
        int s7 = __ldg(&g_csr[e + 7]);
        float2 v0 = __half22float2(__ldg(&g_hsh[s0 * 32 + lane]));
        float2 v1 = __half22float2(__ldg(&g_hsh[s1 * 32 + lane]));
        float2 v2 = __half22float2(__ldg(&g_hsh[s2 * 32 + lane]));
        float2 v3 = __half22float2(__ldg(&g_hsh[s3 * 32 + lane]));
        float2 v4 = __half22float2(__ldg(&g_hsh[s4 * 32 + lane]));
        float2 v5 = __half22float2(__ldg(&g_hsh[s5 * 32 + lane]));
        float2 v6 = __half22float2(__ldg(&g_hsh[s6 * 32 + lane]));
        float2 v7 = __half22float2(__ldg(&g_hsh[s7 * 32 + lane]));
        acc.x += ((v0.x + v1.x) + (v2.x + v3.x)) + ((v4.x + v5.x) + (v6.x + v7.x));
        acc.y += ((v0.y + v1.y) + (v2.y + v3.y)) + ((v4.y + v5.y) + (v6.y + v7.y));
    }
    for (; e < end; e++) {
        int s = __ldg(&g_csr[e]);
        float2 v = __half22float2(__ldg(&g_hsh[s * 32 + lane]));
        acc.x += v.x; acc.y += v.y;
    }

    const float di = g_dinv[node];
    const int c = lane * 2;
    float2 bb = *(const float2*)(b + c);
    float zx = fmaxf(acc.x * di + bb.x, 0.0f);
    float zy = fmaxf(acc.y * di + bb.y, 0.0f);

    if constexpr (FUSE_OUT == 0) {
        *(float2*)(g_z + node * 64 + c) = make_float2(zx, zy);
    } else {
        float2 w = *(const float2*)(Wo + c);
        float sum = zx * w.x + zy * w.y;
        #pragma unroll
        for (int off = 16; off; off >>= 1)
            sum += __shfl_down_sync(0xffffffff, sum, off);
        if (lane == 0) out[node] = sum + bo[0];
    }
}

// ---------------------------------------------------------------------------
extern "C" void kernel_launch(void* const* d_in, const int* in_sizes, int n_in,
                              void* d_out, int out_size) {
    const float* h  = (const float*)d_in[0];
    const void*  ei = d_in[1];               // [2,E]; dtype probed on device
    const float* W1 = (const float*)d_in[2];
    const float* b1 = (const float*)d_in[3];
    const float* W2 = (const float*)d_in[4];
    const float* b2 = (const float*)d_in[5];
    const float* Wo = (const float*)d_in[6];
    const float* bo = (const float*)d_in[7];
    float* out = (float*)d_out;

    cudaStream_t s2;
    cudaStreamCreateWithFlags(&s2, cudaStreamNonBlocking);
    cudaEvent_t eFork, eJoin;
    cudaEventCreateWithFlags(&eFork, cudaEventDisableTiming);
    cudaEventCreateWithFlags(&eJoin, cudaEventDisableTiming);

    // Main stream: init, count, scan (produces dinv needed by gemm epilogue).
    k_init<<<(N_NODES + 255) / 256, 256>>>((const long long*)ei);
    k_count<<<(N_EDGES + 255) / 256, 256>>>(ei);
    k_scan<<<N_SCANB, SCAN_B>>>();

    // Fork gemm0 to overlap with k_fill.
    cudaEventRecord(eFork, 0);
    cudaStreamWaitEvent(s2, eFork, 0);
    k_gemm<0><<<(N_NODES + 63) / 64, 256, 0, s2>>>(h, W1);
    cudaEventRecord(eJoin, s2);

    k_fill<<<(N_EDGES + 255) / 256, 256>>>(ei);

    cudaStreamWaitEvent(0, eJoin, 0);
    k_aggregate<0><<<(N_NODES * 32 + 255) / 256, 256>>>(b1, nullptr, nullptr, nullptr);
    k_gemm<1><<<(N_NODES + 63) / 64, 256>>>(nullptr, W2);
    k_aggregate<1><<<(N_NODES * 32 + 255) / 256, 256>>>(b2, Wo, bo, out);

    cudaEventDestroy(eFork);
    cudaEventDestroy(eJoin);
    cudaStreamDestroy(s2);
}